// round 1
// baseline (speedup 1.0000x reference)
#include <cuda_runtime.h>
#include <math.h>

#define D_MODEL 512
#define NH      8
#define DH      64
#define BB      2
#define SS      2048
#define MTOT    (BB * SS)   // 4096

// ---------------- scratch (no allocations allowed) ----------------
__device__ float g_q[BB * NH * SS * DH];     // [B,H,S,64]
__device__ float g_k[BB * NH * SS * DH];
__device__ float g_v[BB * NH * SS * DH];
__device__ float g_att[BB * SS * D_MODEL];   // [B,S,512]

// ---------------- shared SGEMM mainloop: C(64x64) = A(64xK) * W(64xK)^T ----
// A row-major [M,K], W row-major [N,K]. 256 threads, 4x4 micro-tile.
__device__ __forceinline__ void gemm_mainloop(
    const float* __restrict__ A, const float* __restrict__ W,
    int m0, int n0, int t,
    float (&acc)[4][4], float (*As)[68], float (*Bs)[68])
{
    const int K = D_MODEL;
    const int lr = t >> 2;   // 0..63 tile row
    const int lv = t & 3;    // 0..3  float4 within 16-wide K slab
    const int tx = t & 15, ty = t >> 4;

    for (int k0 = 0; k0 < K; k0 += 16) {
        __syncthreads();
        float4 av = *(const float4*)(A + (size_t)(m0 + lr) * K + k0 + lv * 4);
        float4 bv = *(const float4*)(W + (size_t)(n0 + lr) * K + k0 + lv * 4);
        As[lv * 4 + 0][lr] = av.x; As[lv * 4 + 1][lr] = av.y;
        As[lv * 4 + 2][lr] = av.z; As[lv * 4 + 3][lr] = av.w;
        Bs[lv * 4 + 0][lr] = bv.x; Bs[lv * 4 + 1][lr] = bv.y;
        Bs[lv * 4 + 2][lr] = bv.z; Bs[lv * 4 + 3][lr] = bv.w;
        __syncthreads();
#pragma unroll
        for (int kk = 0; kk < 16; kk++) {
            float4 a = *(const float4*)&As[kk][ty * 4];
            float4 b = *(const float4*)&Bs[kk][tx * 4];
            acc[0][0] += a.x * b.x; acc[0][1] += a.x * b.y; acc[0][2] += a.x * b.z; acc[0][3] += a.x * b.w;
            acc[1][0] += a.y * b.x; acc[1][1] += a.y * b.y; acc[1][2] += a.y * b.z; acc[1][3] += a.y * b.w;
            acc[2][0] += a.z * b.x; acc[2][1] += a.z * b.y; acc[2][2] += a.z * b.z; acc[2][3] += a.z * b.w;
            acc[3][0] += a.w * b.x; acc[3][1] += a.w * b.y; acc[3][2] += a.w * b.z; acc[3][3] += a.w * b.w;
        }
    }
}

// ---------------- fused QKV projection (z selects q/k/v), head-split output -
__global__ __launch_bounds__(256) void proj_qkv_kernel(
    const float* __restrict__ q, const float* __restrict__ k,
    const float* __restrict__ v, const float* __restrict__ W,
    const float* __restrict__ bias)
{
    __shared__ float As[16][68];
    __shared__ float Bs[16][68];
    const float* A = (blockIdx.z == 0) ? q : (blockIdx.z == 1) ? k : v;
    float*       C = (blockIdx.z == 0) ? g_q : (blockIdx.z == 1) ? g_k : g_v;

    const int t = threadIdx.x;
    const int m0 = blockIdx.y * 64, n0 = blockIdx.x * 64;
    float acc[4][4] = {};
    gemm_mainloop(A, W, m0, n0, t, acc, As, Bs);

    const int tx = t & 15, ty = t >> 4;
    const int h = n0 >> 6;                       // 64-wide N tile == one head
    float4 bv = *(const float4*)(bias + n0 + tx * 4);
#pragma unroll
    for (int i = 0; i < 4; i++) {
        int m_ = m0 + ty * 4 + i;
        int b = m_ >> 11, s = m_ & (SS - 1);
        float4 o;
        o.x = acc[i][0] + bv.x; o.y = acc[i][1] + bv.y;
        o.z = acc[i][2] + bv.z; o.w = acc[i][3] + bv.w;
        *(float4*)(C + (((size_t)(b * NH + h) * SS + s) * DH) + tx * 4) = o;
    }
}

// ---------------- output projection: d_out = g_att @ Wc^T + bc --------------
__global__ __launch_bounds__(256) void out_proj_kernel(
    const float* __restrict__ W, const float* __restrict__ bias,
    float* __restrict__ C)
{
    __shared__ float As[16][68];
    __shared__ float Bs[16][68];
    const int t = threadIdx.x;
    const int m0 = blockIdx.y * 64, n0 = blockIdx.x * 64;
    float acc[4][4] = {};
    gemm_mainloop(g_att, W, m0, n0, t, acc, As, Bs);

    const int tx = t & 15, ty = t >> 4;
    float4 bv = *(const float4*)(bias + n0 + tx * 4);
#pragma unroll
    for (int i = 0; i < 4; i++) {
        int m_ = m0 + ty * 4 + i;
        float4 o;
        o.x = acc[i][0] + bv.x; o.y = acc[i][1] + bv.y;
        o.z = acc[i][2] + bv.z; o.w = acc[i][3] + bv.w;
        *(float4*)(C + (size_t)m_ * D_MODEL + n0 + tx * 4) = o;
    }
}

// ---------------- flash attention: one CTA per (b,h, 64-row q tile) ---------
// smem: Qs[64][64] + Kst[64][68] (d-major, transposed) + Vs[64][64] + Ps[64][68]
#define FLASH_SMEM_FLOATS (64 * 64 + 64 * 68 + 64 * 64 + 64 * 68)
#define FLASH_SMEM_BYTES  (FLASH_SMEM_FLOATS * 4)

__global__ __launch_bounds__(256) void flash_kernel()
{
    extern __shared__ float sm[];
    float (*Qs)[64]  = (float(*)[64])(sm);
    float (*Kst)[68] = (float(*)[68])(sm + 64 * 64);
    float (*Vs)[64]  = (float(*)[64])(sm + 64 * 64 + 64 * 68);
    float (*Ps)[68]  = (float(*)[68])(sm + 2 * 64 * 64 + 64 * 68);

    const int t  = threadIdx.x;
    const int tx = t & 15, ty = t >> 4;
    const int q0 = blockIdx.x * 64;
    const int bh = blockIdx.y;                  // b*8 + h
    const float* Qg = g_q + (size_t)bh * SS * DH;
    const float* Kg = g_k + (size_t)bh * SS * DH;
    const float* Vg = g_v + (size_t)bh * SS * DH;

    // load Q tile, pre-scaled by 1/sqrt(64)
#pragma unroll
    for (int r = 0; r < 4; r++) {
        int idx = t + r * 256;
        int row = idx >> 4, seg = idx & 15;
        float4 qv = *(const float4*)(Qg + (size_t)(q0 + row) * DH + seg * 4);
        float4 sv = make_float4(qv.x * 0.125f, qv.y * 0.125f, qv.z * 0.125f, qv.w * 0.125f);
        *(float4*)&Qs[row][seg * 4] = sv;
    }

    float m[4], l[4], o[4][4];
#pragma unroll
    for (int i = 0; i < 4; i++) {
        m[i] = -1e30f; l[i] = 0.f;
#pragma unroll
        for (int j = 0; j < 4; j++) o[i][j] = 0.f;
    }

    for (int k0 = 0; k0 < SS; k0 += 64) {
        __syncthreads();   // previous PV done before overwriting K/V/P tiles
#pragma unroll
        for (int r = 0; r < 4; r++) {
            int idx = t + r * 256;
            int row = idx >> 4, seg = idx & 15;
            float4 kv = *(const float4*)(Kg + (size_t)(k0 + row) * DH + seg * 4);
            Kst[seg * 4 + 0][row] = kv.x; Kst[seg * 4 + 1][row] = kv.y;
            Kst[seg * 4 + 2][row] = kv.z; Kst[seg * 4 + 3][row] = kv.w;
            float4 vv = *(const float4*)(Vg + (size_t)(k0 + row) * DH + seg * 4);
            *(float4*)&Vs[row][seg * 4] = vv;
        }
        __syncthreads();

        // S tile: s4[i][j] = Q[qrow] . K[kcol]
        float s4[4][4] = {};
#pragma unroll
        for (int d = 0; d < 64; d += 4) {
            float4 k0v = *(const float4*)&Kst[d + 0][tx * 4];
            float4 k1v = *(const float4*)&Kst[d + 1][tx * 4];
            float4 k2v = *(const float4*)&Kst[d + 2][tx * 4];
            float4 k3v = *(const float4*)&Kst[d + 3][tx * 4];
#pragma unroll
            for (int i = 0; i < 4; i++) {
                float4 qv = *(const float4*)&Qs[ty * 4 + i][d];
                s4[i][0] += qv.x * k0v.x + qv.y * k1v.x + qv.z * k2v.x + qv.w * k3v.x;
                s4[i][1] += qv.x * k0v.y + qv.y * k1v.y + qv.z * k2v.y + qv.w * k3v.y;
                s4[i][2] += qv.x * k0v.z + qv.y * k1v.z + qv.z * k2v.z + qv.w * k3v.z;
                s4[i][3] += qv.x * k0v.w + qv.y * k1v.w + qv.z * k2v.w + qv.w * k3v.w;
            }
        }

        // online softmax (row stats reduced across the 16 tx lanes)
#pragma unroll
        for (int i = 0; i < 4; i++) {
            float mx = fmaxf(fmaxf(s4[i][0], s4[i][1]), fmaxf(s4[i][2], s4[i][3]));
#pragma unroll
            for (int off = 8; off >= 1; off >>= 1)
                mx = fmaxf(mx, __shfl_xor_sync(0xffffffffu, mx, off));
            float mn   = fmaxf(m[i], mx);
            float corr = __expf(m[i] - mn);
            m[i] = mn;
            float p0 = __expf(s4[i][0] - mn), p1 = __expf(s4[i][1] - mn);
            float p2 = __expf(s4[i][2] - mn), p3 = __expf(s4[i][3] - mn);
            Ps[ty * 4 + i][tx * 4 + 0] = p0; Ps[ty * 4 + i][tx * 4 + 1] = p1;
            Ps[ty * 4 + i][tx * 4 + 2] = p2; Ps[ty * 4 + i][tx * 4 + 3] = p3;
            float sum = p0 + p1 + p2 + p3;
#pragma unroll
            for (int off = 8; off >= 1; off >>= 1)
                sum += __shfl_xor_sync(0xffffffffu, sum, off);
            l[i] = l[i] * corr + sum;
            o[i][0] *= corr; o[i][1] *= corr; o[i][2] *= corr; o[i][3] *= corr;
        }
        __syncthreads();   // Ps visible to all before PV

        // O += P @ V
#pragma unroll
        for (int k = 0; k < 64; k += 4) {
            float4 v0 = *(const float4*)&Vs[k + 0][tx * 4];
            float4 v1 = *(const float4*)&Vs[k + 1][tx * 4];
            float4 v2 = *(const float4*)&Vs[k + 2][tx * 4];
            float4 v3 = *(const float4*)&Vs[k + 3][tx * 4];
#pragma unroll
            for (int i = 0; i < 4; i++) {
                float4 pv = *(const float4*)&Ps[ty * 4 + i][k];
                o[i][0] += pv.x * v0.x + pv.y * v1.x + pv.z * v2.x + pv.w * v3.x;
                o[i][1] += pv.x * v0.y + pv.y * v1.y + pv.z * v2.y + pv.w * v3.y;
                o[i][2] += pv.x * v0.z + pv.y * v1.z + pv.z * v2.z + pv.w * v3.z;
                o[i][3] += pv.x * v0.w + pv.y * v1.w + pv.z * v2.w + pv.w * v3.w;
            }
        }
    }

    // write concat layout [B,S,512]
    const int b = bh >> 3, h = bh & 7;
#pragma unroll
    for (int i = 0; i < 4; i++) {
        float inv = 1.0f / l[i];
        float4 ov = make_float4(o[i][0] * inv, o[i][1] * inv, o[i][2] * inv, o[i][3] * inv);
        *(float4*)(g_att + ((size_t)b * SS + q0 + ty * 4 + i) * D_MODEL + h * DH + tx * 4) = ov;
    }
}

// ---------------- launch ----------------------------------------------------
extern "C" void kernel_launch(void* const* d_in, const int* in_sizes, int n_in,
                              void* d_out, int out_size)
{
    (void)in_sizes; (void)n_in; (void)out_size;
    const float* q    = (const float*)d_in[0];
    const float* k    = (const float*)d_in[1];
    const float* v    = (const float*)d_in[2];
    const float* Wq_w = (const float*)d_in[3];
    const float* Wq_b = (const float*)d_in[4];
    const float* Wc_w = (const float*)d_in[5];
    const float* Wc_b = (const float*)d_in[6];

    // 1) fused QKV projections into head-split scratch
    proj_qkv_kernel<<<dim3(D_MODEL / 64, MTOT / 64, 3), 256>>>(q, k, v, Wq_w, Wq_b);

    // 2) flash attention (dynamic smem > 48KB needs opt-in; host-side, capture-safe)
    cudaFuncSetAttribute(flash_kernel, cudaFuncAttributeMaxDynamicSharedMemorySize,
                         FLASH_SMEM_BYTES);
    flash_kernel<<<dim3(SS / 64, BB * NH), 256, FLASH_SMEM_BYTES>>>();

    // 3) output projection
    out_proj_kernel<<<dim3(D_MODEL / 64, MTOT / 64), 256>>>(Wc_w, Wc_b, (float*)d_out);
}

// round 3
// speedup vs baseline: 3.3866x; 3.3866x over previous
#include <cuda_runtime.h>
#include <stdint.h>
#include <math.h>

#define D_MODEL 512
#define NH      8
#define DH      64
#define BB      2
#define SS      2048
#define MTOT    (BB * SS)   // 4096

// ---------------- scratch (no allocations allowed) ----------------
__device__ float g_q[BB * NH * SS * DH];     // [B,H,S,64]
__device__ float g_k[BB * NH * SS * DH];     // [B,H,S,64]
__device__ float g_v[BB * NH * DH * SS];     // [B,H,64,S]  (TRANSPOSED)
__device__ float g_att[BB * SS * D_MODEL];   // [B,S,512]

// ---------------- helpers ----------------
__device__ __forceinline__ uint32_t f2tf32(float x) {
    uint32_t r; asm("cvt.rna.tf32.f32 %0, %1;" : "=r"(r) : "f"(x)); return r;
}
// D(16x8,f32) += A(16x8,tf32,row) * B(8x8,tf32,col)
__device__ __forceinline__ void mma_tf32(float* d, const uint32_t* a, const uint32_t* b) {
    asm volatile(
        "mma.sync.aligned.m16n8k8.row.col.f32.tf32.tf32.f32 "
        "{%0,%1,%2,%3}, {%4,%5,%6,%7}, {%8,%9}, {%0,%1,%2,%3};"
        : "+f"(d[0]), "+f"(d[1]), "+f"(d[2]), "+f"(d[3])
        : "r"(a[0]), "r"(a[1]), "r"(a[2]), "r"(a[3]), "r"(b[0]), "r"(b[1]));
}

// ============================================================================
// GEMM: C[4096,512] = A[4096,512] @ W[512,512]^T (+bias)
// CTA tile 128x128, 8 warps (4m x 2n), warp tile 32x64, K chunk 32.
// ============================================================================
struct GemmSmem {
    uint32_t As[128][36];   // pad 36: frag LDS bank = (4*row+col)%32, conflict-free
    uint32_t Ws[128][36];
};

__device__ __forceinline__ void gemm_mainloop_mma(
    const float* __restrict__ A, const float* __restrict__ W,
    int m0, int n0, float (&acc)[2][8][4], GemmSmem& s)
{
    const int t = threadIdx.x, lane = t & 31, wid = t >> 5;
    const int g = lane >> 2, i = lane & 3;
    const int wm = (wid & 3) * 32, wn = (wid >> 2) * 64;

    for (int k0 = 0; k0 < D_MODEL; k0 += 32) {
        __syncthreads();
#pragma unroll
        for (int r = 0; r < 4; r++) {
            int f = t + r * 256;          // 1024 float4 per tile
            int row = f >> 3, c4 = f & 7;
            float4 av = *(const float4*)(A + (size_t)(m0 + row) * D_MODEL + k0 + c4 * 4);
            *(uint4*)&s.As[row][c4 * 4] =
                make_uint4(f2tf32(av.x), f2tf32(av.y), f2tf32(av.z), f2tf32(av.w));
            float4 wv = *(const float4*)(W + (size_t)(n0 + row) * D_MODEL + k0 + c4 * 4);
            *(uint4*)&s.Ws[row][c4 * 4] =
                make_uint4(f2tf32(wv.x), f2tf32(wv.y), f2tf32(wv.z), f2tf32(wv.w));
        }
        __syncthreads();
#pragma unroll
        for (int ks = 0; ks < 4; ks++) {
            const int kc = ks * 8;
            uint32_t af[2][4];
#pragma unroll
            for (int mf = 0; mf < 2; mf++) {
                af[mf][0] = s.As[wm + mf * 16 + g    ][kc + i];
                af[mf][1] = s.As[wm + mf * 16 + g + 8][kc + i];
                af[mf][2] = s.As[wm + mf * 16 + g    ][kc + i + 4];
                af[mf][3] = s.As[wm + mf * 16 + g + 8][kc + i + 4];
            }
#pragma unroll
            for (int nf = 0; nf < 8; nf++) {
                uint32_t bf[2];
                bf[0] = s.Ws[wn + nf * 8 + g][kc + i];
                bf[1] = s.Ws[wn + nf * 8 + g][kc + i + 4];
                mma_tf32(acc[0][nf], af[0], bf);
                mma_tf32(acc[1][nf], af[1], bf);
            }
        }
    }
}

// --- QKV projection: q,k -> [B,H,S,64]; v -> [B,H,64,S] (transposed) ---
__global__ __launch_bounds__(256) void proj_qkv_mma(
    const float* __restrict__ q, const float* __restrict__ k,
    const float* __restrict__ v, const float* __restrict__ W,
    const float* __restrict__ bias)
{
    __shared__ GemmSmem s;
    const float* A = (blockIdx.z == 0) ? q : (blockIdx.z == 1) ? k : v;
    const int m0 = blockIdx.y * 128, n0 = blockIdx.x * 128;
    float acc[2][8][4] = {};
    gemm_mainloop_mma(A, W, m0, n0, acc, s);

    const int t = threadIdx.x, lane = t & 31, wid = t >> 5;
    const int g = lane >> 2, i = lane & 3;
    const int wm = (wid & 3) * 32, wn = (wid >> 2) * 64;

#pragma unroll
    for (int mf = 0; mf < 2; mf++) {
        int mA = m0 + wm + mf * 16 + g, mB = mA + 8;
        int bA = mA >> 11, sA = mA & (SS - 1);
        int bB = mB >> 11, sB = mB & (SS - 1);
#pragma unroll
        for (int nf = 0; nf < 8; nf++) {
            int n = n0 + wn + nf * 8 + 2 * i;
            int h = n >> 6, c = n & 63;
            float b0 = bias[n], b1 = bias[n + 1];
            if (blockIdx.z == 2) {
                g_v[(((size_t)bA * NH + h) * DH + c    ) * SS + sA] = acc[mf][nf][0] + b0;
                g_v[(((size_t)bA * NH + h) * DH + c + 1) * SS + sA] = acc[mf][nf][1] + b1;
                g_v[(((size_t)bB * NH + h) * DH + c    ) * SS + sB] = acc[mf][nf][2] + b0;
                g_v[(((size_t)bB * NH + h) * DH + c + 1) * SS + sB] = acc[mf][nf][3] + b1;
            } else {
                float* C = (blockIdx.z == 0) ? g_q : g_k;
                *(float2*)&C[(((size_t)bA * NH + h) * SS + sA) * DH + c] =
                    make_float2(acc[mf][nf][0] + b0, acc[mf][nf][1] + b1);
                *(float2*)&C[(((size_t)bB * NH + h) * SS + sB) * DH + c] =
                    make_float2(acc[mf][nf][2] + b0, acc[mf][nf][3] + b1);
            }
        }
    }
}

// --- output projection: d_out = g_att @ Wc^T + bc ---
__global__ __launch_bounds__(256) void out_proj_mma(
    const float* __restrict__ W, const float* __restrict__ bias,
    float* __restrict__ C)
{
    __shared__ GemmSmem s;
    const int m0 = blockIdx.y * 128, n0 = blockIdx.x * 128;
    float acc[2][8][4] = {};
    gemm_mainloop_mma(g_att, W, m0, n0, acc, s);

    const int t = threadIdx.x, lane = t & 31, wid = t >> 5;
    const int g = lane >> 2, i = lane & 3;
    const int wm = (wid & 3) * 32, wn = (wid >> 2) * 64;

#pragma unroll
    for (int mf = 0; mf < 2; mf++) {
        int mA = m0 + wm + mf * 16 + g, mB = mA + 8;
#pragma unroll
        for (int nf = 0; nf < 8; nf++) {
            int n = n0 + wn + nf * 8 + 2 * i;
            float b0 = bias[n], b1 = bias[n + 1];
            *(float2*)&C[(size_t)mA * D_MODEL + n] =
                make_float2(acc[mf][nf][0] + b0, acc[mf][nf][1] + b1);
            *(float2*)&C[(size_t)mB * D_MODEL + n] =
                make_float2(acc[mf][nf][2] + b0, acc[mf][nf][3] + b1);
        }
    }
}

// ============================================================================
// Flash attention on mma.sync tf32.
// Q tile 128 rows, 8 warps: warp w owns rows [16w,16w+16). Full kv width 64
// per tile -> row softmax is warp-local (shfl over lanes ^1,^2).
// Q fragments live in registers for the whole kernel.
// smem: Ks[64][68], Vt[64][68], Ps[128][68]  (pad 68 -> conflict-free frags)
// ============================================================================
#define FL_SMEM_WORDS (64 * 68 + 64 * 68 + 128 * 68)
#define FL_SMEM_BYTES (FL_SMEM_WORDS * 4)

__global__ __launch_bounds__(256) void flash_mma()
{
    extern __shared__ uint32_t smf[];
    uint32_t (*Ks)[68] = (uint32_t(*)[68])smf;
    uint32_t (*Vt)[68] = (uint32_t(*)[68])(smf + 64 * 68);
    uint32_t (*Ps)[68] = (uint32_t(*)[68])(smf + 2 * 64 * 68);

    const int t = threadIdx.x, lane = t & 31, w = t >> 5;
    const int g = lane >> 2, i = lane & 3;
    const int q0 = blockIdx.x * 128;
    const int bh = blockIdx.y;
    const float* Qg = g_q + (size_t)bh * SS * DH;
    const float* Kg = g_k + (size_t)bh * SS * DH;
    const float* Vg = g_v + (size_t)bh * DH * SS;   // [64][S]

    // Q fragments (pre-scaled by 1/sqrt(64)=0.125), resident in registers
    const int rA = q0 + w * 16 + g, rB = rA + 8;
    uint32_t qf[8][4];
#pragma unroll
    for (int ks = 0; ks < 8; ks++) {
        qf[ks][0] = f2tf32(Qg[(size_t)rA * DH + ks * 8 + i    ] * 0.125f);
        qf[ks][1] = f2tf32(Qg[(size_t)rB * DH + ks * 8 + i    ] * 0.125f);
        qf[ks][2] = f2tf32(Qg[(size_t)rA * DH + ks * 8 + i + 4] * 0.125f);
        qf[ks][3] = f2tf32(Qg[(size_t)rB * DH + ks * 8 + i + 4] * 0.125f);
    }

    float mrow[2] = {-1e30f, -1e30f}, lrow[2] = {0.f, 0.f};
    float of[8][4] = {};

    for (int kv0 = 0; kv0 < SS; kv0 += 64) {
        __syncthreads();   // prev PV reads of Ks/Vt/Ps done
        // stage K [64][64] and Vt [64][64] (V already d-major in global)
#pragma unroll
        for (int r = 0; r < 4; r++) {
            int f = t + r * 256;             // 1024 float4 each
            int row = f >> 4, c4 = f & 15;
            float4 kv4 = *(const float4*)(Kg + (size_t)(kv0 + row) * DH + c4 * 4);
            *(uint4*)&Ks[row][c4 * 4] =
                make_uint4(f2tf32(kv4.x), f2tf32(kv4.y), f2tf32(kv4.z), f2tf32(kv4.w));
            float4 vv4 = *(const float4*)(Vg + (size_t)row * SS + kv0 + c4 * 4);
            *(uint4*)&Vt[row][c4 * 4] =
                make_uint4(f2tf32(vv4.x), f2tf32(vv4.y), f2tf32(vv4.z), f2tf32(vv4.w));
        }
        __syncthreads();

        // S = Q Kt  (warp rows rA/rB x kv 64)
        float sf[8][4] = {};
#pragma unroll
        for (int ks = 0; ks < 8; ks++) {
            const int kc = ks * 8;
#pragma unroll
            for (int nf = 0; nf < 8; nf++) {
                uint32_t bf[2];
                bf[0] = Ks[nf * 8 + g][kc + i];
                bf[1] = Ks[nf * 8 + g][kc + i + 4];
                mma_tf32(sf[nf], qf[ks], bf);
            }
        }

        // online softmax, rows rA (c0,c1) and rB (c2,c3)
        float mxA = -1e30f, mxB = -1e30f;
#pragma unroll
        for (int nf = 0; nf < 8; nf++) {
            mxA = fmaxf(mxA, fmaxf(sf[nf][0], sf[nf][1]));
            mxB = fmaxf(mxB, fmaxf(sf[nf][2], sf[nf][3]));
        }
        mxA = fmaxf(mxA, __shfl_xor_sync(0xffffffffu, mxA, 1));
        mxA = fmaxf(mxA, __shfl_xor_sync(0xffffffffu, mxA, 2));
        mxB = fmaxf(mxB, __shfl_xor_sync(0xffffffffu, mxB, 1));
        mxB = fmaxf(mxB, __shfl_xor_sync(0xffffffffu, mxB, 2));
        float mnA = fmaxf(mrow[0], mxA), mnB = fmaxf(mrow[1], mxB);
        float corrA = __expf(mrow[0] - mnA), corrB = __expf(mrow[1] - mnB);
        mrow[0] = mnA; mrow[1] = mnB;

        float sumA = 0.f, sumB = 0.f;
        const int prA = w * 16 + g, prB = prA + 8;
#pragma unroll
        for (int nf = 0; nf < 8; nf++) {
            float p00 = __expf(sf[nf][0] - mnA), p01 = __expf(sf[nf][1] - mnA);
            float p10 = __expf(sf[nf][2] - mnB), p11 = __expf(sf[nf][3] - mnB);
            sumA += p00 + p01; sumB += p10 + p11;
            *(uint2*)&Ps[prA][nf * 8 + 2 * i] = make_uint2(f2tf32(p00), f2tf32(p01));
            *(uint2*)&Ps[prB][nf * 8 + 2 * i] = make_uint2(f2tf32(p10), f2tf32(p11));
        }
        sumA += __shfl_xor_sync(0xffffffffu, sumA, 1);
        sumA += __shfl_xor_sync(0xffffffffu, sumA, 2);
        sumB += __shfl_xor_sync(0xffffffffu, sumB, 1);
        sumB += __shfl_xor_sync(0xffffffffu, sumB, 2);
        lrow[0] = lrow[0] * corrA + sumA;
        lrow[1] = lrow[1] * corrB + sumB;
#pragma unroll
        for (int nf = 0; nf < 8; nf++) {
            of[nf][0] *= corrA; of[nf][1] *= corrA;
            of[nf][2] *= corrB; of[nf][3] *= corrB;
        }
        __syncwarp();   // Ps rows are warp-private: warp-level visibility suffices

        // O += P V   (k = kv)
#pragma unroll
        for (int ks = 0; ks < 8; ks++) {
            const int kc = ks * 8;
            uint32_t pf[4];
            pf[0] = Ps[prA][kc + i];
            pf[1] = Ps[prB][kc + i];
            pf[2] = Ps[prA][kc + i + 4];
            pf[3] = Ps[prB][kc + i + 4];
#pragma unroll
            for (int nf = 0; nf < 8; nf++) {
                uint32_t bf[2];
                bf[0] = Vt[nf * 8 + g][kc + i];
                bf[1] = Vt[nf * 8 + g][kc + i + 4];
                mma_tf32(of[nf], pf, bf);
            }
        }
    }

    // epilogue: normalize, write concat layout [B,S,512]
    const int b = bh >> 3, h = bh & 7;
    const float invA = 1.0f / lrow[0], invB = 1.0f / lrow[1];
#pragma unroll
    for (int nf = 0; nf < 8; nf++) {
        int d = nf * 8 + 2 * i;
        *(float2*)&g_att[((size_t)b * SS + rA) * D_MODEL + h * DH + d] =
            make_float2(of[nf][0] * invA, of[nf][1] * invA);
        *(float2*)&g_att[((size_t)b * SS + rB) * D_MODEL + h * DH + d] =
            make_float2(of[nf][2] * invB, of[nf][3] * invB);
    }
}

// ---------------- launch ----------------------------------------------------
extern "C" void kernel_launch(void* const* d_in, const int* in_sizes, int n_in,
                              void* d_out, int out_size)
{
    (void)in_sizes; (void)n_in; (void)out_size;
    const float* q    = (const float*)d_in[0];
    const float* k    = (const float*)d_in[1];
    const float* v    = (const float*)d_in[2];
    const float* Wq_w = (const float*)d_in[3];
    const float* Wq_b = (const float*)d_in[4];
    const float* Wc_w = (const float*)d_in[5];
    const float* Wc_b = (const float*)d_in[6];

    // 1) QKV projections (tf32 mma)
    proj_qkv_mma<<<dim3(D_MODEL / 128, MTOT / 128, 3), 256>>>(q, k, v, Wq_w, Wq_b);

    // 2) flash attention (tf32 mma)
    cudaFuncSetAttribute(flash_mma, cudaFuncAttributeMaxDynamicSharedMemorySize,
                         FL_SMEM_BYTES);
    flash_mma<<<dim3(SS / 128, BB * NH), 256, FL_SMEM_BYTES>>>();

    // 3) output projection (tf32 mma)
    out_proj_mma<<<dim3(D_MODEL / 128, MTOT / 128), 256>>>(Wc_w, Wc_b, (float*)d_out);
}

// round 4
// speedup vs baseline: 3.5253x; 1.0410x over previous
#include <cuda_runtime.h>
#include <stdint.h>

#define D_MODEL 512
#define NH      8
#define DH      64
#define BB      2
#define SS      2048
#define MTOT    (BB * SS)   // 4096

// ---------------- scratch ----------------
__device__ float g_rq[MTOT * D_MODEL];       // tf32-rounded inputs
__device__ float g_rk[MTOT * D_MODEL];
__device__ float g_rv[MTOT * D_MODEL];
__device__ float g_rwq[D_MODEL * D_MODEL];
__device__ float g_rwc[D_MODEL * D_MODEL];
__device__ float g_q[BB * NH * SS * DH];     // [B,H,S,64], rounded, pre-scaled 0.125
__device__ float g_k[BB * NH * SS * DH];     // [B,H,S,64], rounded
__device__ float g_v[BB * NH * DH * SS];     // [B,H,64,S], rounded (transposed)
__device__ float g_att[MTOT * D_MODEL];      // [B,S,512], rounded

// ---------------- helpers ----------------
__device__ __forceinline__ uint32_t f2tf32(float x) {
    uint32_t r; asm("cvt.rna.tf32.f32 %0, %1;" : "=r"(r) : "f"(x)); return r;
}
__device__ __forceinline__ float roundtf(float x) { return __uint_as_float(f2tf32(x)); }
__device__ __forceinline__ uint32_t smem_u32(const void* p) {
    uint32_t a;
    asm("{ .reg .u64 t; cvta.to.shared.u64 t, %1; cvt.u32.u64 %0, t; }" : "=r"(a) : "l"(p));
    return a;
}
__device__ __forceinline__ void mma_tf32(float* d, const uint32_t* a, const uint32_t* b) {
    asm volatile(
        "mma.sync.aligned.m16n8k8.row.col.f32.tf32.tf32.f32 "
        "{%0,%1,%2,%3}, {%4,%5,%6,%7}, {%8,%9}, {%0,%1,%2,%3};"
        : "+f"(d[0]), "+f"(d[1]), "+f"(d[2]), "+f"(d[3])
        : "r"(a[0]), "r"(a[1]), "r"(a[2]), "r"(a[3]), "r"(b[0]), "r"(b[1]));
}
__device__ __forceinline__ void cp16(uint32_t dst, const void* src) {
    asm volatile("cp.async.cg.shared.global [%0], [%1], 16;" :: "r"(dst), "l"(src));
}
__device__ __forceinline__ void cpcommit() { asm volatile("cp.async.commit_group;"); }
template<int N> __device__ __forceinline__ void cpwait() {
    asm volatile("cp.async.wait_group %0;" :: "n"(N));
}

// ============================================================================
// prep: tf32-round q,k,v,Wq,Wc (bulk bandwidth kernel)
// ============================================================================
#define N1 (MTOT * D_MODEL / 4)
#define NW (D_MODEL * D_MODEL / 4)
#define PREP_TOT (3 * N1 + 2 * NW)

__global__ __launch_bounds__(256) void prep_kernel(
    const float* __restrict__ q, const float* __restrict__ k,
    const float* __restrict__ v, const float* __restrict__ wq,
    const float* __restrict__ wc)
{
    int idx = blockIdx.x * 256 + threadIdx.x;
    const float* src; float* dst; int off;
    if      (idx <     N1)          { src = q;  dst = g_rq;  off = idx; }
    else if (idx < 2 * N1)          { src = k;  dst = g_rk;  off = idx - N1; }
    else if (idx < 3 * N1)          { src = v;  dst = g_rv;  off = idx - 2 * N1; }
    else if (idx < 3 * N1 + NW)     { src = wq; dst = g_rwq; off = idx - 3 * N1; }
    else if (idx < PREP_TOT)        { src = wc; dst = g_rwc; off = idx - 3 * N1 - NW; }
    else return;
    float4 x = ((const float4*)src)[off];
    float4 y = make_float4(roundtf(x.x), roundtf(x.y), roundtf(x.z), roundtf(x.w));
    ((float4*)dst)[off] = y;
}

// ============================================================================
// GEMM: C[4096,512] = A @ W^T (+bias). CTA 128x128, 8 warps (4m x 2n).
// cp.async double-buffered K-chunks of 32. Operands pre-rounded -> zero cvt.
// ============================================================================
#define GS_PAD 36
#define GEMM_SMEM_BYTES (2 * 2 * 128 * GS_PAD * 4)   // 73728

__device__ __forceinline__ void gemm_loop_cp(
    const float* __restrict__ A, const float* __restrict__ W,
    int m0, int n0, float (&acc)[2][8][4], uint32_t* sm, uint32_t sb)
{
    const int t = threadIdx.x, lane = t & 31, wid = t >> 5;
    const int g = lane >> 2, i = lane & 3;
    const int wm = (wid & 3) * 32, wn = (wid >> 2) * 64;
    const uint32_t wBaseOff = 2 * 128 * GS_PAD;      // word offset of W region

    const int frow = t >> 1;                  // copy mapping: 2 threads/row? no:
    (void)frow;
    // copy: per chunk 128 rows x 8 float4 per array; f = t + r*256
    auto issue = [&](int c) {
        const int k0 = c * 32, st = c & 1;
#pragma unroll
        for (int r = 0; r < 4; r++) {
            int f = t + r * 256, row = f >> 3, c4 = f & 7;
            uint32_t so = ((uint32_t)(st * 128 + row) * GS_PAD + c4 * 4) * 4;
            cp16(sb + so, A + (size_t)(m0 + row) * D_MODEL + k0 + c4 * 4);
            cp16(sb + (wBaseOff * 4) + so, W + (size_t)(n0 + row) * D_MODEL + k0 + c4 * 4);
        }
        cpcommit();
    };

    issue(0);
    for (int c = 0; c < 16; c++) {
        __syncthreads();                      // prev reads done before overwrite
        if (c + 1 < 16) { issue(c + 1); cpwait<1>(); }
        else            { cpwait<0>(); }
        __syncthreads();                      // chunk c visible to all
        const uint32_t* As = sm + (uint32_t)(c & 1) * 128 * GS_PAD;
        const uint32_t* Ws = sm + wBaseOff + (uint32_t)(c & 1) * 128 * GS_PAD;
#pragma unroll
        for (int ks = 0; ks < 4; ks++) {
            const int kc = ks * 8;
            uint32_t af[2][4];
#pragma unroll
            for (int mf = 0; mf < 2; mf++) {
                const uint32_t* r0 = As + (uint32_t)(wm + mf * 16 + g) * GS_PAD;
                const uint32_t* r1 = As + (uint32_t)(wm + mf * 16 + g + 8) * GS_PAD;
                af[mf][0] = r0[kc + i];     af[mf][1] = r1[kc + i];
                af[mf][2] = r0[kc + i + 4]; af[mf][3] = r1[kc + i + 4];
            }
#pragma unroll
            for (int nf = 0; nf < 8; nf++) {
                const uint32_t* rw = Ws + (uint32_t)(wn + nf * 8 + g) * GS_PAD;
                uint32_t bf[2] = { rw[kc + i], rw[kc + i + 4] };
                mma_tf32(acc[0][nf], af[0], bf);
                mma_tf32(acc[1][nf], af[1], bf);
            }
        }
    }
}

// --- QKV projection: q -> g_q (x0.125, rounded), k -> g_k, v -> g_v (transposed)
__global__ __launch_bounds__(256) void proj_qkv2(const float* __restrict__ bias)
{
    extern __shared__ uint32_t sm[];
    uint32_t sb = smem_u32(sm);
    const float* A = (blockIdx.z == 0) ? g_rq : (blockIdx.z == 1) ? g_rk : g_rv;
    const int m0 = blockIdx.y * 128, n0 = blockIdx.x * 128;
    float acc[2][8][4] = {};
    gemm_loop_cp(A, g_rwq, m0, n0, acc, sm, sb);

    const int t = threadIdx.x, lane = t & 31, wid = t >> 5;
    const int g = lane >> 2, i = lane & 3;
    const int wm = (wid & 3) * 32, wn = (wid >> 2) * 64;

#pragma unroll
    for (int mf = 0; mf < 2; mf++) {
        int mA = m0 + wm + mf * 16 + g, mB = mA + 8;
        int bA = mA >> 11, sA = mA & (SS - 1);
        int bB = mB >> 11, sB = mB & (SS - 1);
#pragma unroll
        for (int nf = 0; nf < 8; nf++) {
            int n = n0 + wn + nf * 8 + 2 * i;
            int h = n >> 6, cc = n & 63;
            float b0 = bias[n], b1 = bias[n + 1];
            float v0 = acc[mf][nf][0] + b0, v1 = acc[mf][nf][1] + b1;
            float v2 = acc[mf][nf][2] + b0, v3 = acc[mf][nf][3] + b1;
            if (blockIdx.z == 0) {            // Q: scale + round
                *(float2*)&g_q[(((size_t)(bA * NH + h)) * SS + sA) * DH + cc] =
                    make_float2(roundtf(v0 * 0.125f), roundtf(v1 * 0.125f));
                *(float2*)&g_q[(((size_t)(bB * NH + h)) * SS + sB) * DH + cc] =
                    make_float2(roundtf(v2 * 0.125f), roundtf(v3 * 0.125f));
            } else if (blockIdx.z == 1) {     // K: round
                *(float2*)&g_k[(((size_t)(bA * NH + h)) * SS + sA) * DH + cc] =
                    make_float2(roundtf(v0), roundtf(v1));
                *(float2*)&g_k[(((size_t)(bB * NH + h)) * SS + sB) * DH + cc] =
                    make_float2(roundtf(v2), roundtf(v3));
            } else {                          // V: round + transpose [B,H,64,S]
                g_v[(((size_t)(bA * NH + h)) * DH + cc    ) * SS + sA] = roundtf(v0);
                g_v[(((size_t)(bA * NH + h)) * DH + cc + 1) * SS + sA] = roundtf(v1);
                g_v[(((size_t)(bB * NH + h)) * DH + cc    ) * SS + sB] = roundtf(v2);
                g_v[(((size_t)(bB * NH + h)) * DH + cc + 1) * SS + sB] = roundtf(v3);
            }
        }
    }
}

// --- output projection: d_out = g_att @ Wc^T + bc (plain fp32 out) ---
__global__ __launch_bounds__(256) void out_proj2(
    const float* __restrict__ bias, float* __restrict__ C)
{
    extern __shared__ uint32_t sm[];
    uint32_t sb = smem_u32(sm);
    const int m0 = blockIdx.y * 128, n0 = blockIdx.x * 128;
    float acc[2][8][4] = {};
    gemm_loop_cp(g_att, g_rwc, m0, n0, acc, sm, sb);

    const int t = threadIdx.x, lane = t & 31, wid = t >> 5;
    const int g = lane >> 2, i = lane & 3;
    const int wm = (wid & 3) * 32, wn = (wid >> 2) * 64;

#pragma unroll
    for (int mf = 0; mf < 2; mf++) {
        int mA = m0 + wm + mf * 16 + g, mB = mA + 8;
#pragma unroll
        for (int nf = 0; nf < 8; nf++) {
            int n = n0 + wn + nf * 8 + 2 * i;
            float b0 = bias[n], b1 = bias[n + 1];
            *(float2*)&C[(size_t)mA * D_MODEL + n] =
                make_float2(acc[mf][nf][0] + b0, acc[mf][nf][1] + b1);
            *(float2*)&C[(size_t)mB * D_MODEL + n] =
                make_float2(acc[mf][nf][2] + b0, acc[mf][nf][3] + b1);
        }
    }
}

// ============================================================================
// Flash attention. Q tile 128 (8 warps x 16 rows), kv tile 64,
// cp.async double-buffered K/V, P entirely in registers (k-perm absorbed in V).
// ============================================================================
#define FK_PAD 68
#define FV_PAD 72
#define FL_KWORDS (2 * 64 * FK_PAD)
#define FL_SMEM_BYTES ((FL_KWORDS + 2 * 64 * FV_PAD) * 4)   // 71680

__global__ __launch_bounds__(256) void flash2()
{
    extern __shared__ uint32_t fsm[];
    uint32_t sb = smem_u32(fsm);
    const int t = threadIdx.x, lane = t & 31, w = t >> 5;
    const int g = lane >> 2, i = lane & 3;
    const int q0 = blockIdx.x * 128;
    const int bh = blockIdx.y;
    const float* Qg = g_q + (size_t)bh * SS * DH;
    const float* Kg = g_k + (size_t)bh * SS * DH;
    const float* Vg = g_v + (size_t)bh * DH * SS;   // [64][S]

    // Q fragments (already scaled+rounded) resident in registers
    const int rA = q0 + w * 16 + g, rB = rA + 8;
    uint32_t qf[8][4];
#pragma unroll
    for (int ks = 0; ks < 8; ks++) {
        qf[ks][0] = __float_as_uint(Qg[(size_t)rA * DH + ks * 8 + i]);
        qf[ks][1] = __float_as_uint(Qg[(size_t)rB * DH + ks * 8 + i]);
        qf[ks][2] = __float_as_uint(Qg[(size_t)rA * DH + ks * 8 + i + 4]);
        qf[ks][3] = __float_as_uint(Qg[(size_t)rB * DH + ks * 8 + i + 4]);
    }

    auto issueKV = [&](int c) {
        const int kv0 = c * 64, st = c & 1;
#pragma unroll
        for (int r = 0; r < 4; r++) {
            int f = t + r * 256, row = f >> 4, c4 = f & 15;
            cp16(sb + ((uint32_t)(st * 64 + row) * FK_PAD + c4 * 4) * 4,
                 Kg + (size_t)(kv0 + row) * DH + c4 * 4);
            cp16(sb + (FL_KWORDS + (uint32_t)(st * 64 + row) * FV_PAD + c4 * 4) * 4,
                 Vg + (size_t)row * SS + kv0 + c4 * 4);
        }
        cpcommit();
    };

    float mrow[2] = {-1e30f, -1e30f}, lrow[2] = {0.f, 0.f};
    float of[8][4] = {};

    issueKV(0);
    for (int c = 0; c < SS / 64; c++) {
        __syncthreads();
        if (c + 1 < SS / 64) { issueKV(c + 1); cpwait<1>(); }
        else                 { cpwait<0>(); }
        __syncthreads();
        const uint32_t* Kb = fsm + (uint32_t)(c & 1) * 64 * FK_PAD;
        const uint32_t* Vb = fsm + FL_KWORDS + (uint32_t)(c & 1) * 64 * FV_PAD;

        // S = Q K^T
        float sf[8][4] = {};
#pragma unroll
        for (int ks = 0; ks < 8; ks++) {
            const int kc = ks * 8;
#pragma unroll
            for (int nf = 0; nf < 8; nf++) {
                const uint32_t* rk = Kb + (uint32_t)(nf * 8 + g) * FK_PAD;
                uint32_t bf[2] = { rk[kc + i], rk[kc + i + 4] };
                mma_tf32(sf[nf], qf[ks], bf);
            }
        }

        // online softmax (rows rA: sf[.][0,1]; rB: sf[.][2,3])
        float mxA = -1e30f, mxB = -1e30f;
#pragma unroll
        for (int nf = 0; nf < 8; nf++) {
            mxA = fmaxf(mxA, fmaxf(sf[nf][0], sf[nf][1]));
            mxB = fmaxf(mxB, fmaxf(sf[nf][2], sf[nf][3]));
        }
        mxA = fmaxf(mxA, __shfl_xor_sync(0xffffffffu, mxA, 1));
        mxA = fmaxf(mxA, __shfl_xor_sync(0xffffffffu, mxA, 2));
        mxB = fmaxf(mxB, __shfl_xor_sync(0xffffffffu, mxB, 1));
        mxB = fmaxf(mxB, __shfl_xor_sync(0xffffffffu, mxB, 2));
        float mnA = fmaxf(mrow[0], mxA), mnB = fmaxf(mrow[1], mxB);
        float corrA = __expf(mrow[0] - mnA), corrB = __expf(mrow[1] - mnB);
        mrow[0] = mnA; mrow[1] = mnB;

        float sumA = 0.f, sumB = 0.f;
        uint32_t pf[8][4];
#pragma unroll
        for (int nf = 0; nf < 8; nf++) {
            float p00 = __expf(sf[nf][0] - mnA), p01 = __expf(sf[nf][1] - mnA);
            float p10 = __expf(sf[nf][2] - mnB), p11 = __expf(sf[nf][3] - mnB);
            sumA += p00 + p01; sumB += p10 + p11;
            pf[nf][0] = f2tf32(p00); pf[nf][1] = f2tf32(p01);
            pf[nf][2] = f2tf32(p10); pf[nf][3] = f2tf32(p11);
        }
        sumA += __shfl_xor_sync(0xffffffffu, sumA, 1);
        sumA += __shfl_xor_sync(0xffffffffu, sumA, 2);
        sumB += __shfl_xor_sync(0xffffffffu, sumB, 1);
        sumB += __shfl_xor_sync(0xffffffffu, sumB, 2);
        lrow[0] = lrow[0] * corrA + sumA;
        lrow[1] = lrow[1] * corrB + sumB;
#pragma unroll
        for (int nf = 0; nf < 8; nf++) {
            of[nf][0] *= corrA; of[nf][1] *= corrA;
            of[nf][2] *= corrB; of[nf][3] *= corrB;
        }

        // O += P V, k-permutation sigma(s)=2s / 2s+1 absorbed into V addressing:
        // A frag = {P[g][kc+2i], P[g+8][kc+2i], P[g][kc+2i+1], P[g+8][kc+2i+1]}
        //        = {pf[ks][0], pf[ks][2], pf[ks][1], pf[ks][3]}
        // B frag = Vt[n][kc+2i], Vt[n][kc+2i+1]  (adjacent -> one LDS.64)
#pragma unroll
        for (int ks = 0; ks < 8; ks++) {
            const int kc = ks * 8;
            uint32_t af2[4] = { pf[ks][0], pf[ks][2], pf[ks][1], pf[ks][3] };
#pragma unroll
            for (int nf = 0; nf < 8; nf++) {
                uint2 bv = *(const uint2*)(Vb + (uint32_t)(nf * 8 + g) * FV_PAD + kc + 2 * i);
                uint32_t bf2[2] = { bv.x, bv.y };
                mma_tf32(of[nf], af2, bf2);
            }
        }
    }

    // epilogue: normalize, round (g_att feeds tf32 out_proj), concat layout
    const int b = bh >> 3, h = bh & 7;
    const float invA = 1.0f / lrow[0], invB = 1.0f / lrow[1];
#pragma unroll
    for (int nf = 0; nf < 8; nf++) {
        int d = nf * 8 + 2 * i;
        *(float2*)&g_att[((size_t)b * SS + rA) * D_MODEL + h * DH + d] =
            make_float2(roundtf(of[nf][0] * invA), roundtf(of[nf][1] * invA));
        *(float2*)&g_att[((size_t)b * SS + rB) * D_MODEL + h * DH + d] =
            make_float2(roundtf(of[nf][2] * invB), roundtf(of[nf][3] * invB));
    }
}

// ---------------- launch ----------------------------------------------------
extern "C" void kernel_launch(void* const* d_in, const int* in_sizes, int n_in,
                              void* d_out, int out_size)
{
    (void)in_sizes; (void)n_in; (void)out_size;
    const float* q    = (const float*)d_in[0];
    const float* k    = (const float*)d_in[1];
    const float* v    = (const float*)d_in[2];
    const float* Wq_w = (const float*)d_in[3];
    const float* Wq_b = (const float*)d_in[4];
    const float* Wc_w = (const float*)d_in[5];
    const float* Wc_b = (const float*)d_in[6];

    cudaFuncSetAttribute(proj_qkv2, cudaFuncAttributeMaxDynamicSharedMemorySize,
                         GEMM_SMEM_BYTES);
    cudaFuncSetAttribute(out_proj2, cudaFuncAttributeMaxDynamicSharedMemorySize,
                         GEMM_SMEM_BYTES);
    cudaFuncSetAttribute(flash2, cudaFuncAttributeMaxDynamicSharedMemorySize,
                         FL_SMEM_BYTES);

    // 0) tf32 pre-round of all GEMM operands
    prep_kernel<<<(PREP_TOT + 255) / 256, 256>>>(q, k, v, Wq_w, Wc_w);

    // 1) QKV projections
    proj_qkv2<<<dim3(D_MODEL / 128, MTOT / 128, 3), 256, GEMM_SMEM_BYTES>>>(Wq_b);

    // 2) flash attention
    flash2<<<dim3(SS / 128, BB * NH), 256, FL_SMEM_BYTES>>>();

    // 3) output projection
    out_proj2<<<dim3(D_MODEL / 128, MTOT / 128), 256, GEMM_SMEM_BYTES>>>(Wc_b, (float*)d_out);
}

// round 5
// speedup vs baseline: 4.5040x; 1.2776x over previous
#include <cuda_runtime.h>
#include <stdint.h>

#define D_MODEL 512
#define NH      8
#define DH      64
#define BB      2
#define SS      2048
#define MTOT    (BB * SS)   // 4096

// ---------------- scratch ----------------
__device__ float g_rq[MTOT * D_MODEL];       // tf32-rounded inputs
__device__ float g_rk[MTOT * D_MODEL];
__device__ float g_rv[MTOT * D_MODEL];
__device__ float g_rwq[D_MODEL * D_MODEL];
__device__ float g_rwc[D_MODEL * D_MODEL];
__device__ float g_q[BB * NH * SS * DH];     // [B,H,S,64], rounded, pre-scaled 0.125
__device__ float g_k[BB * NH * SS * DH];     // [B,H,S,64], rounded
__device__ float g_v[BB * NH * DH * SS];     // [B,H,64,S], rounded (transposed)
__device__ float g_att[MTOT * D_MODEL];      // [B,S,512], rounded

// ---------------- helpers ----------------
__device__ __forceinline__ uint32_t f2tf32(float x) {
    uint32_t r; asm("cvt.rna.tf32.f32 %0, %1;" : "=r"(r) : "f"(x)); return r;
}
__device__ __forceinline__ float roundtf(float x) { return __uint_as_float(f2tf32(x)); }
__device__ __forceinline__ uint32_t smem_u32(const void* p) {
    uint32_t a;
    asm("{ .reg .u64 t; cvta.to.shared.u64 t, %1; cvt.u32.u64 %0, t; }" : "=r"(a) : "l"(p));
    return a;
}
__device__ __forceinline__ void mma_tf32(float* d, const uint32_t* a, const uint32_t* b) {
    asm volatile(
        "mma.sync.aligned.m16n8k8.row.col.f32.tf32.tf32.f32 "
        "{%0,%1,%2,%3}, {%4,%5,%6,%7}, {%8,%9}, {%0,%1,%2,%3};"
        : "+f"(d[0]), "+f"(d[1]), "+f"(d[2]), "+f"(d[3])
        : "r"(a[0]), "r"(a[1]), "r"(a[2]), "r"(a[3]), "r"(b[0]), "r"(b[1]));
}
__device__ __forceinline__ void cp16(uint32_t dst, const void* src) {
    asm volatile("cp.async.cg.shared.global [%0], [%1], 16;" :: "r"(dst), "l"(src));
}
__device__ __forceinline__ void cpcommit() { asm volatile("cp.async.commit_group;"); }
template<int N> __device__ __forceinline__ void cpwait() {
    asm volatile("cp.async.wait_group %0;" :: "n"(N));
}

// ============================================================================
// prep: tf32-round q,k,v,Wq,Wc
// ============================================================================
#define N1 (MTOT * D_MODEL / 4)
#define NW (D_MODEL * D_MODEL / 4)
#define PREP_TOT (3 * N1 + 2 * NW)

__global__ __launch_bounds__(256) void prep_kernel(
    const float* __restrict__ q, const float* __restrict__ k,
    const float* __restrict__ v, const float* __restrict__ wq,
    const float* __restrict__ wc)
{
    int idx = blockIdx.x * 256 + threadIdx.x;
    const float* src; float* dst; int off;
    if      (idx <     N1)      { src = q;  dst = g_rq;  off = idx; }
    else if (idx < 2 * N1)      { src = k;  dst = g_rk;  off = idx - N1; }
    else if (idx < 3 * N1)      { src = v;  dst = g_rv;  off = idx - 2 * N1; }
    else if (idx < 3 * N1 + NW) { src = wq; dst = g_rwq; off = idx - 3 * N1; }
    else if (idx < PREP_TOT)    { src = wc; dst = g_rwc; off = idx - 3 * N1 - NW; }
    else return;
    float4 x = ((const float4*)src)[off];
    ((float4*)dst)[off] = make_float4(roundtf(x.x), roundtf(x.y), roundtf(x.z), roundtf(x.w));
}

// ============================================================================
// GEMM: C = A @ W^T (+bias). CTA tile 64x64, 4 warps (2m x 2n), warp 32x32.
// K-chunk 32, cp.async double-buffered. Row stride 40 words; permuted-k
// fragment loads (adjacent u2) -> all LDS.64, conflict-free (8g+2i banks).
// ============================================================================
#define GPAD 40
#define GWOFF (2 * 64 * GPAD)     // word offset of W region (5120)

__device__ __forceinline__ void gemm_loop64(
    const float* __restrict__ A, const float* __restrict__ W,
    int m0, int n0, float (&acc)[2][4][4], uint32_t* smg, uint32_t sb)
{
    const int t = threadIdx.x, lane = t & 31, wid = t >> 5;
    const int g = lane >> 2, i = lane & 3;
    const int wm = (wid & 1) * 32, wn = (wid >> 1) * 32;

    auto issue = [&](int c) {
        const int k0 = c * 32, st = c & 1;
#pragma unroll
        for (int r = 0; r < 4; r++) {
            int f = t + r * 128;          // 512 float4 per operand
            int row = f >> 3, c4 = f & 7;
            uint32_t so = ((uint32_t)(st * 64 + row) * GPAD + c4 * 4) * 4;
            cp16(sb + so, A + (size_t)(m0 + row) * D_MODEL + k0 + c4 * 4);
            cp16(sb + GWOFF * 4 + so, W + (size_t)(n0 + row) * D_MODEL + k0 + c4 * 4);
        }
        cpcommit();
    };

    issue(0);
    for (int c = 0; c < 16; c++) {
        __syncthreads();
        if (c + 1 < 16) { issue(c + 1); cpwait<1>(); }
        else            { cpwait<0>(); }
        __syncthreads();
        const uint32_t* As = smg + (uint32_t)(c & 1) * 64 * GPAD;
        const uint32_t* Ws = smg + GWOFF + (uint32_t)(c & 1) * 64 * GPAD;
#pragma unroll
        for (int ks = 0; ks < 4; ks++) {
            const int kc = ks * 8;
            uint32_t af[2][4];
#pragma unroll
            for (int mf = 0; mf < 2; mf++) {
                const uint32_t* r0 = As + (uint32_t)(wm + mf * 16 + g) * GPAD + kc + 2 * i;
                const uint32_t* r1 = r0 + 8 * GPAD;
                uint2 a0 = *(const uint2*)r0;
                uint2 a1 = *(const uint2*)r1;
                af[mf][0] = a0.x; af[mf][1] = a1.x; af[mf][2] = a0.y; af[mf][3] = a1.y;
            }
#pragma unroll
            for (int nf = 0; nf < 4; nf++) {
                uint2 bv = *(const uint2*)(Ws + (uint32_t)(wn + nf * 8 + g) * GPAD + kc + 2 * i);
                uint32_t bf[2] = { bv.x, bv.y };
                mma_tf32(acc[0][nf], af[0], bf);
                mma_tf32(acc[1][nf], af[1], bf);
            }
        }
    }
}

// --- QKV projection ---
__global__ __launch_bounds__(128, 4) void proj_qkv3(const float* __restrict__ bias)
{
    __shared__ uint32_t smg[2 * 2 * 64 * GPAD];   // 40960 B
    uint32_t sb = smem_u32(smg);
    const float* A = (blockIdx.z == 0) ? g_rq : (blockIdx.z == 1) ? g_rk : g_rv;
    const int m0 = blockIdx.y * 64, n0 = blockIdx.x * 64;
    float acc[2][4][4] = {};
    gemm_loop64(A, g_rwq, m0, n0, acc, smg, sb);

    const int t = threadIdx.x, lane = t & 31, wid = t >> 5;
    const int g = lane >> 2, i = lane & 3;
    const int wm = (wid & 1) * 32, wn = (wid >> 1) * 32;

#pragma unroll
    for (int mf = 0; mf < 2; mf++) {
        int mA = m0 + wm + mf * 16 + g, mB = mA + 8;
        int bA = mA >> 11, sA = mA & (SS - 1);
        int bB = mB >> 11, sB = mB & (SS - 1);
#pragma unroll
        for (int nf = 0; nf < 4; nf++) {
            int n = n0 + wn + nf * 8 + 2 * i;
            int h = n >> 6, cc = n & 63;
            float b0 = bias[n], b1 = bias[n + 1];
            float v0 = acc[mf][nf][0] + b0, v1 = acc[mf][nf][1] + b1;
            float v2 = acc[mf][nf][2] + b0, v3 = acc[mf][nf][3] + b1;
            if (blockIdx.z == 0) {
                *(float2*)&g_q[(((size_t)(bA * NH + h)) * SS + sA) * DH + cc] =
                    make_float2(roundtf(v0 * 0.125f), roundtf(v1 * 0.125f));
                *(float2*)&g_q[(((size_t)(bB * NH + h)) * SS + sB) * DH + cc] =
                    make_float2(roundtf(v2 * 0.125f), roundtf(v3 * 0.125f));
            } else if (blockIdx.z == 1) {
                *(float2*)&g_k[(((size_t)(bA * NH + h)) * SS + sA) * DH + cc] =
                    make_float2(roundtf(v0), roundtf(v1));
                *(float2*)&g_k[(((size_t)(bB * NH + h)) * SS + sB) * DH + cc] =
                    make_float2(roundtf(v2), roundtf(v3));
            } else {
                g_v[(((size_t)(bA * NH + h)) * DH + cc    ) * SS + sA] = roundtf(v0);
                g_v[(((size_t)(bA * NH + h)) * DH + cc + 1) * SS + sA] = roundtf(v1);
                g_v[(((size_t)(bB * NH + h)) * DH + cc    ) * SS + sB] = roundtf(v2);
                g_v[(((size_t)(bB * NH + h)) * DH + cc + 1) * SS + sB] = roundtf(v3);
            }
        }
    }
}

// --- output projection ---
__global__ __launch_bounds__(128, 4) void out_proj3(
    const float* __restrict__ bias, float* __restrict__ C)
{
    __shared__ uint32_t smg[2 * 2 * 64 * GPAD];
    uint32_t sb = smem_u32(smg);
    const int m0 = blockIdx.y * 64, n0 = blockIdx.x * 64;
    float acc[2][4][4] = {};
    gemm_loop64(g_att, g_rwc, m0, n0, acc, smg, sb);

    const int t = threadIdx.x, lane = t & 31, wid = t >> 5;
    const int g = lane >> 2, i = lane & 3;
    const int wm = (wid & 1) * 32, wn = (wid >> 1) * 32;

#pragma unroll
    for (int mf = 0; mf < 2; mf++) {
        int mA = m0 + wm + mf * 16 + g, mB = mA + 8;
#pragma unroll
        for (int nf = 0; nf < 4; nf++) {
            int n = n0 + wn + nf * 8 + 2 * i;
            float b0 = bias[n], b1 = bias[n + 1];
            *(float2*)&C[(size_t)mA * D_MODEL + n] =
                make_float2(acc[mf][nf][0] + b0, acc[mf][nf][1] + b1);
            *(float2*)&C[(size_t)mB * D_MODEL + n] =
                make_float2(acc[mf][nf][2] + b0, acc[mf][nf][3] + b1);
        }
    }
}

// ============================================================================
// Flash attention. Q tile 128, 4 warps, warp m=32 (mf=2) -> every K/V
// B-fragment feeds 2 MMAs (halves smem read traffic). kv tile 64,
// cp.async double-buffered, pad 72 (conflict-free permuted u2 loads).
// ============================================================================
#define FPAD 72
#define FVOFF (2 * 64 * FPAD)                 // word offset of V region (9216)
#define FL_SMEM_BYTES (2 * FVOFF * 4)         // 73728

__global__ __launch_bounds__(128, 2) void flash3()
{
    extern __shared__ uint32_t fsm[];
    uint32_t sb = smem_u32(fsm);
    const int t = threadIdx.x, lane = t & 31, w = t >> 5;
    const int g = lane >> 2, i = lane & 3;
    const int q0 = blockIdx.x * 128;
    const int bh = blockIdx.y;
    const float* Qg = g_q + (size_t)bh * SS * DH;
    const float* Kg = g_k + (size_t)bh * SS * DH;
    const float* Vg = g_v + (size_t)bh * DH * SS;   // [64][S]

    // Q fragments: warp w owns rows q0 + w*32 + {mf*16 + g, +8}; already
    // scaled+rounded. Permuted-k: slots (0,2)=cols 2i,2i+1 of row r0; (1,3)=r1.
    uint32_t qf[2][8][4];
#pragma unroll
    for (int mf = 0; mf < 2; mf++) {
        const int r0 = q0 + w * 32 + mf * 16 + g, r1 = r0 + 8;
#pragma unroll
        for (int ks = 0; ks < 8; ks++) {
            uint2 a0 = *(const uint2*)(Qg + (size_t)r0 * DH + ks * 8 + 2 * i);
            uint2 a1 = *(const uint2*)(Qg + (size_t)r1 * DH + ks * 8 + 2 * i);
            qf[mf][ks][0] = a0.x; qf[mf][ks][1] = a1.x;
            qf[mf][ks][2] = a0.y; qf[mf][ks][3] = a1.y;
        }
    }

    auto issueKV = [&](int c) {
        const int kv0 = c * 64, st = c & 1;
#pragma unroll
        for (int r = 0; r < 8; r++) {
            int f = t + r * 128, row = f >> 4, c4 = f & 15;   // 1024 f4 each
            cp16(sb + ((uint32_t)(st * 64 + row) * FPAD + c4 * 4) * 4,
                 Kg + (size_t)(kv0 + row) * DH + c4 * 4);
            cp16(sb + (FVOFF + (uint32_t)(st * 64 + row) * FPAD + c4 * 4) * 4,
                 Vg + (size_t)row * SS + kv0 + c4 * 4);
        }
        cpcommit();
    };

    float mr[2][2] = {{-1e30f, -1e30f}, {-1e30f, -1e30f}};
    float lr[2][2] = {};
    float of[2][8][4] = {};

    issueKV(0);
    for (int c = 0; c < SS / 64; c++) {
        __syncthreads();
        if (c + 1 < SS / 64) { issueKV(c + 1); cpwait<1>(); }
        else                 { cpwait<0>(); }
        __syncthreads();
        const uint32_t* Kb = fsm + (uint32_t)(c & 1) * 64 * FPAD;
        const uint32_t* Vb = fsm + FVOFF + (uint32_t)(c & 1) * 64 * FPAD;

        // S = Q K^T (permuted-k: B frag = adjacent u2)
        float sf[2][8][4] = {};
#pragma unroll
        for (int ks = 0; ks < 8; ks++) {
            const int kc = ks * 8;
#pragma unroll
            for (int nf = 0; nf < 8; nf++) {
                uint2 kv2 = *(const uint2*)(Kb + (uint32_t)(nf * 8 + g) * FPAD + kc + 2 * i);
                uint32_t bf[2] = { kv2.x, kv2.y };
                mma_tf32(sf[0][nf], qf[0][ks], bf);
                mma_tf32(sf[1][nf], qf[1][ks], bf);
            }
        }

        // online softmax; rows: c0,c1 -> r0 (g), c2,c3 -> r1 (g+8), per mf
        uint32_t (&sfu)[2][8][4] = reinterpret_cast<uint32_t(&)[2][8][4]>(sf);
#pragma unroll
        for (int mf = 0; mf < 2; mf++) {
            float mxA = -1e30f, mxB = -1e30f;
#pragma unroll
            for (int nf = 0; nf < 8; nf++) {
                mxA = fmaxf(mxA, fmaxf(sf[mf][nf][0], sf[mf][nf][1]));
                mxB = fmaxf(mxB, fmaxf(sf[mf][nf][2], sf[mf][nf][3]));
            }
            mxA = fmaxf(mxA, __shfl_xor_sync(0xffffffffu, mxA, 1));
            mxA = fmaxf(mxA, __shfl_xor_sync(0xffffffffu, mxA, 2));
            mxB = fmaxf(mxB, __shfl_xor_sync(0xffffffffu, mxB, 1));
            mxB = fmaxf(mxB, __shfl_xor_sync(0xffffffffu, mxB, 2));
            float mnA = fmaxf(mr[mf][0], mxA), mnB = fmaxf(mr[mf][1], mxB);
            float corrA = __expf(mr[mf][0] - mnA), corrB = __expf(mr[mf][1] - mnB);
            mr[mf][0] = mnA; mr[mf][1] = mnB;

            float sumA = 0.f, sumB = 0.f;
#pragma unroll
            for (int nf = 0; nf < 8; nf++) {
                float p00 = __expf(sf[mf][nf][0] - mnA), p01 = __expf(sf[mf][nf][1] - mnA);
                float p10 = __expf(sf[mf][nf][2] - mnB), p11 = __expf(sf[mf][nf][3] - mnB);
                sumA += p00 + p01; sumB += p10 + p11;
                sfu[mf][nf][0] = f2tf32(p00); sfu[mf][nf][1] = f2tf32(p01);
                sfu[mf][nf][2] = f2tf32(p10); sfu[mf][nf][3] = f2tf32(p11);
            }
            sumA += __shfl_xor_sync(0xffffffffu, sumA, 1);
            sumA += __shfl_xor_sync(0xffffffffu, sumA, 2);
            sumB += __shfl_xor_sync(0xffffffffu, sumB, 1);
            sumB += __shfl_xor_sync(0xffffffffu, sumB, 2);
            lr[mf][0] = lr[mf][0] * corrA + sumA;
            lr[mf][1] = lr[mf][1] * corrB + sumB;
#pragma unroll
            for (int nf = 0; nf < 8; nf++) {
                of[mf][nf][0] *= corrA; of[mf][nf][1] *= corrA;
                of[mf][nf][2] *= corrB; of[mf][nf][3] *= corrB;
            }
        }

        // O += P V  (k-perm absorbed into V addressing; same trick as round 4)
#pragma unroll
        for (int ks = 0; ks < 8; ks++) {
            const int kc = ks * 8;
            uint32_t af0[4] = { sfu[0][ks][0], sfu[0][ks][2], sfu[0][ks][1], sfu[0][ks][3] };
            uint32_t af1[4] = { sfu[1][ks][0], sfu[1][ks][2], sfu[1][ks][1], sfu[1][ks][3] };
#pragma unroll
            for (int nf = 0; nf < 8; nf++) {
                uint2 vv2 = *(const uint2*)(Vb + (uint32_t)(nf * 8 + g) * FPAD + kc + 2 * i);
                uint32_t bf[2] = { vv2.x, vv2.y };
                mma_tf32(of[0][nf], af0, bf);
                mma_tf32(of[1][nf], af1, bf);
            }
        }
    }

    // epilogue
    const int b = bh >> 3, h = bh & 7;
#pragma unroll
    for (int mf = 0; mf < 2; mf++) {
        const int r0 = q0 + w * 32 + mf * 16 + g, r1 = r0 + 8;
        const float invA = 1.0f / lr[mf][0], invB = 1.0f / lr[mf][1];
#pragma unroll
        for (int nf = 0; nf < 8; nf++) {
            int d = nf * 8 + 2 * i;
            *(float2*)&g_att[((size_t)b * SS + r0) * D_MODEL + h * DH + d] =
                make_float2(roundtf(of[mf][nf][0] * invA), roundtf(of[mf][nf][1] * invA));
            *(float2*)&g_att[((size_t)b * SS + r1) * D_MODEL + h * DH + d] =
                make_float2(roundtf(of[mf][nf][2] * invB), roundtf(of[mf][nf][3] * invB));
        }
    }
}

// ---------------- launch ----------------------------------------------------
extern "C" void kernel_launch(void* const* d_in, const int* in_sizes, int n_in,
                              void* d_out, int out_size)
{
    (void)in_sizes; (void)n_in; (void)out_size;
    const float* q    = (const float*)d_in[0];
    const float* k    = (const float*)d_in[1];
    const float* v    = (const float*)d_in[2];
    const float* Wq_w = (const float*)d_in[3];
    const float* Wq_b = (const float*)d_in[4];
    const float* Wc_w = (const float*)d_in[5];
    const float* Wc_b = (const float*)d_in[6];

    cudaFuncSetAttribute(flash3, cudaFuncAttributeMaxDynamicSharedMemorySize,
                         FL_SMEM_BYTES);

    prep_kernel<<<(PREP_TOT + 255) / 256, 256>>>(q, k, v, Wq_w, Wc_w);
    proj_qkv3<<<dim3(D_MODEL / 64, MTOT / 64, 3), 128>>>(Wq_b);
    flash3<<<dim3(SS / 128, BB * NH), 128, FL_SMEM_BYTES>>>();
    out_proj3<<<dim3(D_MODEL / 64, MTOT / 64), 128>>>(Wc_b, (float*)d_out);
}